// round 3
// baseline (speedup 1.0000x reference)
#include <cuda_runtime.h>
#include <cuda_bf16.h>
#include <cstdint>

// Problem dims
#define BQ    16
#define NNODE 2048
#define EDIM  8192
#define DIMIN 64
#define DH    32
#define MDIM  NNODE          // 2048  (GEMM M = n)
#define NDIM  (BQ*DH)        // 512   (GEMM N = b*32+h)
#define KDIM  EDIM           // 8192  (GEMM K = e)

// GEMM tiling
#define TM 128
#define TN 128
#define BK 64
#define STAGES 3
#define NCHUNK (KDIM/BK)       // 128
#define REG_BYTES 16384        // one 128x64 bf16 tile (rows of 128B, SW128)
#define STAGE_BYTES (4*REG_BYTES)
#define SMEM_STAGE0 1024
#define SMEM_DYN (SMEM_STAGE0 + STAGES*STAGE_BYTES)   // 197632

// tcgen05 is an arch-specific ("a") feature: only emit its PTX in the sm_103a pass.
#if defined(__CUDA_ARCH__) && (defined(__CUDA_ARCH_FEAT_SM103_ALL) || \
    (defined(__CUDA_ARCH_SPECIFIC__) && (__CUDA_ARCH_SPECIFIC__ == 1030)))
#define USE_TCGEN05 1
#else
#define USE_TCGEN05 0
#endif

// ---------------- scratch (device globals; no allocations allowed) ----------
__device__ __align__(256) __nv_bfloat16 g_Ahi[(size_t)MDIM*KDIM];
__device__ __align__(256) __nv_bfloat16 g_Alo[(size_t)MDIM*KDIM];
__device__ __align__(256) __nv_bfloat16 g_Xhi[(size_t)NDIM*KDIM];  // [c][e]
__device__ __align__(256) __nv_bfloat16 g_Xlo[(size_t)NDIM*KDIM];

// ---------------- PTX helpers (arch-neutral) --------------------------------
static __device__ __forceinline__ uint32_t smem_u32(const void* p) {
    uint32_t a;
    asm("{ .reg .u64 t; cvta.to.shared.u64 t, %1; cvt.u32.u64 %0, t; }"
        : "=r"(a) : "l"(p));
    return a;
}

#define MBARRIER_INIT(addr, cnt) \
    asm volatile("mbarrier.init.shared.b64 [%0], %1;" :: "r"((uint32_t)(addr)), "r"((uint32_t)(cnt)) : "memory")

#define MBARRIER_WAIT_PARITY(mbar_smem_addr, phase_parity) do { \
    uint32_t _mbar = (uint32_t)(mbar_smem_addr); \
    uint32_t _parity = (uint32_t)(phase_parity); \
    uint32_t _done; \
    asm volatile( \
        "{\n\t" \
        ".reg .pred p;\n\t" \
        "mbarrier.try_wait.parity.acquire.cta.shared::cta.b64 p, [%1], %2;\n\t" \
        "selp.b32 %0, 1, 0, p;\n\t" \
        "}" \
        : "=r"(_done) : "r"(_mbar), "r"(_parity) : "memory"); \
    if (!_done) { \
        asm volatile( \
            "{\n\t" \
            ".reg .pred P1;\n\t" \
            "WAIT_LOOP_%=:\n\t" \
            "mbarrier.try_wait.parity.acquire.cta.shared::cta.b64 P1, [%0], %1, 0x989680;\n\t" \
            "@P1 bra.uni WAIT_DONE_%=;\n\t" \
            "bra.uni WAIT_LOOP_%=;\n\t" \
            "WAIT_DONE_%=:\n\t" \
            "}" \
            :: "r"(_mbar), "r"(_parity) : "memory"); \
    } \
} while (0)

#if USE_TCGEN05
// ---------------- tcgen05 helpers (sm_103a pass only) ------------------------
#define TCGEN05_ALLOC(smem_result_addr, nCols) \
    asm volatile("tcgen05.alloc.cta_group::1.sync.aligned.shared::cta.b32 [%0], %1;" \
        :: "r"((uint32_t)(smem_result_addr)), "r"((uint32_t)(nCols)) : "memory")
#define TCGEN05_DEALLOC(tmem_addr, nCols) \
    asm volatile("tcgen05.dealloc.cta_group::1.sync.aligned.b32 %0, %1;" :: "r"(tmem_addr), "r"(nCols))
#define TCGEN05_RELINQUISH() \
    asm volatile("tcgen05.relinquish_alloc_permit.cta_group::1.sync.aligned;")
#define TCGEN05_COMMIT(mbar_smem_addr) \
    asm volatile("tcgen05.commit.cta_group::1.mbarrier::arrive::one.shared::cluster.b64 [%0];" \
        :: "r"((uint32_t)(mbar_smem_addr)) : "memory")
#define TCGEN05_WAIT_LD()  asm volatile("tcgen05.wait::ld.sync.aligned;" ::: "memory")
#define TCGEN05_FENCE_BEFORE() asm volatile("tcgen05.fence::before_thread_sync;" ::: "memory")
#define TCGEN05_FENCE_AFTER()  asm volatile("tcgen05.fence::after_thread_sync;" ::: "memory")
#define FENCE_PROXY_ASYNC_CTA() asm volatile("fence.proxy.async.shared::cta;" ::: "memory")

#define TCGEN05_LD_32X32B_X32(r, tmem_addr) \
    asm volatile( \
        "tcgen05.ld.sync.aligned.32x32b.x32.b32 " \
        "{%0, %1, %2, %3, %4, %5, %6, %7, " \
        " %8, %9, %10, %11, %12, %13, %14, %15, " \
        " %16, %17, %18, %19, %20, %21, %22, %23, " \
        " %24, %25, %26, %27, %28, %29, %30, %31}, [%32];" \
        : "=r"((r)[0]),  "=r"((r)[1]),  "=r"((r)[2]),  "=r"((r)[3]), \
          "=r"((r)[4]),  "=r"((r)[5]),  "=r"((r)[6]),  "=r"((r)[7]), \
          "=r"((r)[8]),  "=r"((r)[9]),  "=r"((r)[10]), "=r"((r)[11]), \
          "=r"((r)[12]), "=r"((r)[13]), "=r"((r)[14]), "=r"((r)[15]), \
          "=r"((r)[16]), "=r"((r)[17]), "=r"((r)[18]), "=r"((r)[19]), \
          "=r"((r)[20]), "=r"((r)[21]), "=r"((r)[22]), "=r"((r)[23]), \
          "=r"((r)[24]), "=r"((r)[25]), "=r"((r)[26]), "=r"((r)[27]), \
          "=r"((r)[28]), "=r"((r)[29]), "=r"((r)[30]), "=r"((r)[31]) \
        : "r"(tmem_addr))

// SW128 SMEM descriptor (K-major, version=1, SBO=64, LBO=1)
static constexpr uint64_t SMEM_DESC_BASE_SW128 =
    (uint64_t(2)  << 61) | (uint64_t(1) << 46) | (uint64_t(64) << 32) | (uint64_t(1) << 16);
#define MAKE_SMEM_DESC(base_addr) (SMEM_DESC_BASE_SW128 | ((uint64_t)((base_addr) >> 4) & 0x3FFF))

static __device__ __forceinline__ void mma_f16_ss_cg1(
    uint32_t d_tmem, uint64_t a_desc, uint64_t b_desc, uint32_t idesc, bool acc)
{
    uint32_t en = acc ? 1u : 0u;
    asm volatile(
        "{\n\t"
        ".reg .pred p;\n\t"
        "setp.ne.u32 p, %4, 0;\n\t"
        "tcgen05.mma.cta_group::1.kind::f16 [%0], %1, %2, %3, {%5, %5, %5, %5}, p;\n\t"
        "}"
        :: "r"(d_tmem), "l"(a_desc), "l"(b_desc), "r"(idesc), "r"(en), "r"(0u)
        : "memory");
}
#endif // USE_TCGEN05

// idesc: dtype=F32(1<<4), atype=BF16(1<<7), btype=BF16(1<<10), N/8<<17, M/16<<24
static constexpr uint32_t MMA_IDESC =
    0x490u | ((TN / 8) << 17) | ((TM / 16) << 24);

// ---------------- kernel 1: A = w*inci + b  ->  bf16 hi/lo split -------------
__global__ void __launch_bounds__(256) split_A_kernel(
    const float* __restrict__ w, const float* __restrict__ inci, const float* __restrict__ b)
{
    size_t i = (size_t)blockIdx.x * blockDim.x + threadIdx.x;   // float4 index
    float4 wv = reinterpret_cast<const float4*>(w)[i];
    float4 iv = reinterpret_cast<const float4*>(inci)[i];
    float4 bv = reinterpret_cast<const float4*>(b)[i];
    float a0 = fmaf(wv.x, iv.x, bv.x);
    float a1 = fmaf(wv.y, iv.y, bv.y);
    float a2 = fmaf(wv.z, iv.z, bv.z);
    float a3 = fmaf(wv.w, iv.w, bv.w);

    __nv_bfloat16 h0 = __float2bfloat16(a0), h1 = __float2bfloat16(a1);
    __nv_bfloat16 h2 = __float2bfloat16(a2), h3 = __float2bfloat16(a3);
    __nv_bfloat16 l0 = __float2bfloat16(a0 - __bfloat162float(h0));
    __nv_bfloat16 l1 = __float2bfloat16(a1 - __bfloat162float(h1));
    __nv_bfloat16 l2 = __float2bfloat16(a2 - __bfloat162float(h2));
    __nv_bfloat16 l3 = __float2bfloat16(a3 - __bfloat162float(h3));

    ushort4 hv = make_ushort4(__bfloat16_as_ushort(h0), __bfloat16_as_ushort(h1),
                              __bfloat16_as_ushort(h2), __bfloat16_as_ushort(h3));
    ushort4 lv = make_ushort4(__bfloat16_as_ushort(l0), __bfloat16_as_ushort(l1),
                              __bfloat16_as_ushort(l2), __bfloat16_as_ushort(l3));
    reinterpret_cast<ushort4*>(g_Ahi)[i] = hv;
    reinterpret_cast<ushort4*>(g_Alo)[i] = lv;
}

// ---------------- kernel 2: xe = relu(in @ W + bias), transposed + split -----
__global__ void __launch_bounds__(1024) xe_kernel(
    const float* __restrict__ in, const float* __restrict__ W, const float* __restrict__ bx)
{
    __shared__ float Ws[DIMIN][DH];        // [64][32]
    __shared__ float ins[32][DIMIN];       // [32][64]
    __shared__ uint32_t tr[32][33];        // [h][e_local], padded

    int tx = threadIdx.x, ty = threadIdx.y;
    int e0 = blockIdx.x * 32;
    int b  = blockIdx.y;
    int flat = ty * 32 + tx;

    reinterpret_cast<float*>(Ws)[flat]        = W[flat];
    reinterpret_cast<float*>(Ws)[flat + 1024] = W[flat + 1024];
    size_t row = ((size_t)b * EDIM + e0 + ty) * DIMIN;
    ins[ty][tx]      = in[row + tx];
    ins[ty][tx + 32] = in[row + tx + 32];
    __syncthreads();

    float acc = bx[tx];
#pragma unroll
    for (int d = 0; d < DIMIN; d++)
        acc = fmaf(ins[ty][d], Ws[d][tx], acc);
    acc = fmaxf(acc, 0.0f);

    __nv_bfloat16 h = __float2bfloat16(acc);
    __nv_bfloat16 l = __float2bfloat16(acc - __bfloat162float(h));
    tr[tx][ty] = (uint32_t)__bfloat16_as_ushort(h) | ((uint32_t)__bfloat16_as_ushort(l) << 16);
    __syncthreads();

    uint32_t v = tr[ty][tx];                // h = ty, e_local = tx
    size_t off = (size_t)(b * 32 + ty) * KDIM + e0 + tx;
    g_Xhi[off] = __ushort_as_bfloat16((unsigned short)(v & 0xffffu));
    g_Xlo[off] = __ushort_as_bfloat16((unsigned short)(v >> 16));
}

// ---------------- kernel 3: GEMM ---------------------------------------------
#if USE_TCGEN05
static __device__ __forceinline__ void load_region(
    uint32_t sbase, const __nv_bfloat16* __restrict__ grow, int k0, int t)
{
#pragma unroll
    for (int j = 0; j < 8; j++) {
        int idx = j * 128 + t;                 // 1024 16B-chunks per region
        int r = idx >> 3, g = idx & 7;
        const void* gp = grow + (size_t)r * KDIM + k0 + g * 8;
        uint32_t off = (uint32_t)(r * 128 + g * 16);
        uint32_t so  = sbase + (off ^ ((off >> 3) & 0x70));
        asm volatile("cp.async.cg.shared.global [%0], [%1], 16;" :: "r"(so), "l"(gp));
    }
}
#endif

__global__ void __launch_bounds__(160, 1)
gemm_kernel(float* __restrict__ out)
{
    extern __shared__ char smem[];
    const int tid = threadIdx.x;
    const int m0 = blockIdx.x * TM;
    const int c0 = blockIdx.y * TN;

#if USE_TCGEN05
    uint32_t sb = smem_u32(smem);
    // barriers: full[s] @ sb+16+8s (cnt 128), empty[s] @ sb+64+8s (cnt 1), done @ sb+112 (cnt 1)
    if (tid == 0) {
#pragma unroll
        for (int s = 0; s < STAGES; s++) {
            MBARRIER_INIT(sb + 16 + 8 * s, 128);
            MBARRIER_INIT(sb + 64 + 8 * s, 1);
        }
        MBARRIER_INIT(sb + 112, 1);
    }
    __syncthreads();

    if ((tid >> 5) == 0) TCGEN05_ALLOC(sb + 0, 128);
    __syncthreads();
    uint32_t tmem;
    asm volatile("ld.shared.b32 %0, [%1];" : "=r"(tmem) : "r"(sb + 0));

    if (tid < 128) {
        // ---- producer: cp.async loaders ----
        const __nv_bfloat16* gA0 = g_Ahi + (size_t)m0 * KDIM;
        const __nv_bfloat16* gA1 = g_Alo + (size_t)m0 * KDIM;
        const __nv_bfloat16* gB0 = g_Xhi + (size_t)c0 * KDIM;
        const __nv_bfloat16* gB1 = g_Xlo + (size_t)c0 * KDIM;
        int s = 0, ph = 1;                       // first empty-wait passes immediately
        for (int ch = 0; ch < NCHUNK; ch++) {
            MBARRIER_WAIT_PARITY(sb + 64 + 8 * s, ph);
            uint32_t stb = sb + SMEM_STAGE0 + s * STAGE_BYTES;
            int k0 = ch * BK;
            load_region(stb,                 gA0, k0, tid);
            load_region(stb + REG_BYTES,     gA1, k0, tid);
            load_region(stb + 2 * REG_BYTES, gB0, k0, tid);
            load_region(stb + 3 * REG_BYTES, gB1, k0, tid);
            // .noinc: async arrive counts toward the init count of 128.
            // (non-.noinc increments pending at issue -> net zero -> deadlock; that
            //  was the R2 hang.)
            asm volatile("cp.async.mbarrier.arrive.noinc.shared::cta.b64 [%0];"
                         :: "r"(sb + 16 + 8 * s) : "memory");
            if (++s == STAGES) { s = 0; ph ^= 1; }
        }
    } else if (tid == 128) {
        // ---- consumer: single-thread MMA issuer ----
        int s = 0, ph = 0;
        bool first = true;
        for (int ch = 0; ch < NCHUNK; ch++) {
            MBARRIER_WAIT_PARITY(sb + 16 + 8 * s, ph);
            FENCE_PROXY_ASYNC_CTA();             // generic(cp.async) -> async-proxy(tcgen05)
            uint32_t stb = sb + SMEM_STAGE0 + s * STAGE_BYTES;
            uint64_t dAhi = MAKE_SMEM_DESC(stb);
            uint64_t dAlo = MAKE_SMEM_DESC(stb + REG_BYTES);
            uint64_t dBhi = MAKE_SMEM_DESC(stb + 2 * REG_BYTES);
            uint64_t dBlo = MAKE_SMEM_DESC(stb + 3 * REG_BYTES);
#pragma unroll
            for (int k = 0; k < 4; k++) {        // 4 x K16 per 64-K chunk
                mma_f16_ss_cg1(tmem, dAhi + k * 2, dBhi + k * 2, MMA_IDESC, !first);
                first = false;
                mma_f16_ss_cg1(tmem, dAhi + k * 2, dBlo + k * 2, MMA_IDESC, true);
                mma_f16_ss_cg1(tmem, dAlo + k * 2, dBhi + k * 2, MMA_IDESC, true);
            }
            TCGEN05_COMMIT(sb + 64 + 8 * s);     // frees stage when MMAs complete
            if (++s == STAGES) { s = 0; ph ^= 1; }
        }
        TCGEN05_COMMIT(sb + 112);                // tracks all prior MMAs
    }

    __syncthreads();
    MBARRIER_WAIT_PARITY(sb + 112, 0);
    TCGEN05_FENCE_AFTER();

    if (tid < 128) {
        int n = m0 + tid;
#pragma unroll
        for (int p = 0; p < 4; p++) {
            uint32_t r[32];
            TCGEN05_LD_32X32B_X32(r, tmem + p * 32);
            TCGEN05_WAIT_LD();
            int bb = (c0 >> 5) + p;              // batch index for this 32-col group
            float4* o4 = reinterpret_cast<float4*>(out + (((size_t)bb * NNODE + n) << 5));
#pragma unroll
            for (int q = 0; q < 8; q++)
                o4[q] = make_float4(__uint_as_float(r[4 * q]),     __uint_as_float(r[4 * q + 1]),
                                    __uint_as_float(r[4 * q + 2]), __uint_as_float(r[4 * q + 3]));
        }
        TCGEN05_FENCE_BEFORE();
    }
    __syncthreads();
    if ((tid >> 5) == 0) {
        TCGEN05_RELINQUISH();
        TCGEN05_DEALLOC(tmem, 128);
    }
#else
    // ---------------- SIMT fp32 fallback (non-'a' compilation pass) ----------
    if (tid >= 128) return;
    float* As = reinterpret_cast<float*>(smem);            // [128][65]
    float* Bs = As + 128 * 65;                             // [64][128]

    const int tx = tid & 7;        // n-group: 16 cols
    const int ty = tid >> 3;       // m-group: 8 rows
    float acc[8][16];
#pragma unroll
    for (int i = 0; i < 8; i++)
#pragma unroll
        for (int j = 0; j < 16; j++) acc[i][j] = 0.0f;

    for (int ch = 0; ch < NCHUNK; ch++) {
        int k0 = ch * BK;
        {
            const uint4* ph4 = reinterpret_cast<const uint4*>(g_Ahi + (size_t)(m0 + tid) * KDIM + k0);
            const uint4* pl4 = reinterpret_cast<const uint4*>(g_Alo + (size_t)(m0 + tid) * KDIM + k0);
#pragma unroll
            for (int v = 0; v < 8; v++) {
                uint4 hv = ph4[v], lv = pl4[v];
                const unsigned short* hs = reinterpret_cast<const unsigned short*>(&hv);
                const unsigned short* ls = reinterpret_cast<const unsigned short*>(&lv);
#pragma unroll
                for (int e = 0; e < 8; e++)
                    As[tid * 65 + v * 8 + e] =
                        __bfloat162float(__ushort_as_bfloat16(hs[e])) +
                        __bfloat162float(__ushort_as_bfloat16(ls[e]));
            }
        }
        {
            const uint4* ph4 = reinterpret_cast<const uint4*>(g_Xhi + (size_t)(c0 + tid) * KDIM + k0);
            const uint4* pl4 = reinterpret_cast<const uint4*>(g_Xlo + (size_t)(c0 + tid) * KDIM + k0);
#pragma unroll
            for (int v = 0; v < 8; v++) {
                uint4 hv = ph4[v], lv = pl4[v];
                const unsigned short* hs = reinterpret_cast<const unsigned short*>(&hv);
                const unsigned short* ls = reinterpret_cast<const unsigned short*>(&lv);
#pragma unroll
                for (int e = 0; e < 8; e++)
                    Bs[(v * 8 + e) * 128 + tid] =
                        __bfloat162float(__ushort_as_bfloat16(hs[e])) +
                        __bfloat162float(__ushort_as_bfloat16(ls[e]));
            }
        }
        asm volatile("bar.sync 1, 128;" ::: "memory");
#pragma unroll 4
        for (int k = 0; k < BK; k++) {
            float a[8], bvx[16];
#pragma unroll
            for (int i = 0; i < 8; i++) a[i] = As[(ty * 8 + i) * 65 + k];
#pragma unroll
            for (int j = 0; j < 16; j++) bvx[j] = Bs[k * 128 + tx * 16 + j];
#pragma unroll
            for (int i = 0; i < 8; i++)
#pragma unroll
                for (int j = 0; j < 16; j++)
                    acc[i][j] = fmaf(a[i], bvx[j], acc[i][j]);
        }
        asm volatile("bar.sync 1, 128;" ::: "memory");
    }
#pragma unroll
    for (int i = 0; i < 8; i++) {
        int n = m0 + ty * 8 + i;
#pragma unroll
        for (int j = 0; j < 16; j++) {
            int c = c0 + tx * 16 + j;
            out[(((size_t)(c >> 5) * NNODE + n) << 5) + (c & 31)] = acc[i][j];
        }
    }
#endif
}

// ---------------- launch ----------------------------------------------------
extern "C" void kernel_launch(void* const* d_in, const int* in_sizes, int n_in,
                              void* d_out, int out_size)
{
    const float* inputs = (const float*)d_in[0];   // [16, 8192, 64]
    const float* W_xes  = (const float*)d_in[1];   // [64, 32]
    const float* b_xes  = (const float*)d_in[2];   // [32]
    const float* inci   = (const float*)d_in[3];   // [2048, 8192]
    const float* w      = (const float*)d_in[4];   // [2048, 8192]
    const float* b      = (const float*)d_in[5];   // [2048, 8192]
    float* out = (float*)d_out;                    // [16, 2048, 32]

    // 1) A = w*inci + b -> bf16 hi/lo
    {
        size_t n4 = (size_t)MDIM * KDIM / 4;
        split_A_kernel<<<(unsigned)(n4 / 256), 256>>>(w, inci, b);
    }
    // 2) xe = relu(inputs @ W + bias), transposed to [c][e], bf16 hi/lo
    {
        dim3 grid(EDIM / 32, BQ), blk(32, 32);
        xe_kernel<<<grid, blk>>>(inputs, W_xes, b_xes);
    }
    // 3) GEMM (tcgen05 on sm_103a cubin; SIMT fallback otherwise)
    {
        cudaFuncSetAttribute(gemm_kernel, cudaFuncAttributeMaxDynamicSharedMemorySize, SMEM_DYN);
        dim3 grid(MDIM / TM, NDIM / TN);           // 16 x 4
        gemm_kernel<<<grid, 160, SMEM_DYN>>>(out);
    }
}

// round 4
// speedup vs baseline: 1.1564x; 1.1564x over previous
#include <cuda_runtime.h>
#include <cuda_bf16.h>
#include <cstdint>

// Problem dims
#define BQ    16
#define NNODE 2048
#define EDIM  8192
#define DIMIN 64
#define DH    32
#define MDIM  NNODE          // 2048  (GEMM M = n)
#define NDIM  (BQ*DH)        // 512   (GEMM N = b*32+h)
#define KDIM  EDIM           // 8192  (GEMM K = e)

// GEMM tiling: cg2 pair covers 256(M) x 128(N); split-K=2
#define TMP   256            // M per cluster pair
#define TN    128
#define BK    64
#define KSPLIT 2
#define CHUNKS (KDIM/BK/KSPLIT)   // 64 chunks per CTA
#define STAGES 4
#define A_REG 16384          // 128 rows x 128B (one of hi/lo)
#define B_REG 8192           // 64 rows x 128B (this CTA's N-half, one of hi/lo)
#define STAGE_BYTES (2*A_REG + 2*B_REG)   // 49152
#define SMEM_STAGE0 1024
#define SMEM_DYN (SMEM_STAGE0 + STAGES*STAGE_BYTES)   // 197632

// tcgen05 is an arch-specific ("a") feature: only emit its PTX in the sm_103a pass.
#if defined(__CUDA_ARCH__) && (defined(__CUDA_ARCH_FEAT_SM103_ALL) || \
    (defined(__CUDA_ARCH_SPECIFIC__) && (__CUDA_ARCH_SPECIFIC__ == 1030)))
#define USE_TCGEN05 1
#else
#define USE_TCGEN05 0
#endif

// ---------------- scratch (device globals; no allocations allowed) ----------
__device__ __align__(256) __nv_bfloat16 g_Ahi[(size_t)MDIM*KDIM];
__device__ __align__(256) __nv_bfloat16 g_Alo[(size_t)MDIM*KDIM];
__device__ __align__(256) __nv_bfloat16 g_Xhi[(size_t)NDIM*KDIM];  // [c][e]
__device__ __align__(256) __nv_bfloat16 g_Xlo[(size_t)NDIM*KDIM];

// ---------------- PTX helpers (arch-neutral) --------------------------------
static __device__ __forceinline__ uint32_t smem_u32(const void* p) {
    uint32_t a;
    asm("{ .reg .u64 t; cvta.to.shared.u64 t, %1; cvt.u32.u64 %0, t; }"
        : "=r"(a) : "l"(p));
    return a;
}

#define MBARRIER_INIT(addr, cnt) \
    asm volatile("mbarrier.init.shared.b64 [%0], %1;" :: "r"((uint32_t)(addr)), "r"((uint32_t)(cnt)) : "memory")

// cta-scope acquire wait (local data)
#define MBARRIER_WAIT_PARITY(mbar_smem_addr, phase_parity) do { \
    uint32_t _mbar = (uint32_t)(mbar_smem_addr); \
    uint32_t _parity = (uint32_t)(phase_parity); \
    uint32_t _done; \
    asm volatile( \
        "{\n\t" \
        ".reg .pred p;\n\t" \
        "mbarrier.try_wait.parity.acquire.cta.shared::cta.b64 p, [%1], %2;\n\t" \
        "selp.b32 %0, 1, 0, p;\n\t" \
        "}" \
        : "=r"(_done) : "r"(_mbar), "r"(_parity) : "memory"); \
    if (!_done) { \
        asm volatile( \
            "{\n\t" \
            ".reg .pred P1;\n\t" \
            "WAIT_LOOP_%=:\n\t" \
            "mbarrier.try_wait.parity.acquire.cta.shared::cta.b64 P1, [%0], %1, 0x989680;\n\t" \
            "@P1 bra.uni WAIT_DONE_%=;\n\t" \
            "bra.uni WAIT_LOOP_%=;\n\t" \
            "WAIT_DONE_%=:\n\t" \
            "}" \
            :: "r"(_mbar), "r"(_parity) : "memory"); \
    } \
} while (0)

#if USE_TCGEN05
// cluster-scope acquire wait (consumer observing peer-CTA writes via relay arrive)
#define MBARRIER_WAIT_PARITY_CLU(mbar_smem_addr, phase_parity) do { \
    uint32_t _mbar = (uint32_t)(mbar_smem_addr); \
    uint32_t _parity = (uint32_t)(phase_parity); \
    uint32_t _done; \
    asm volatile( \
        "{\n\t" \
        ".reg .pred p;\n\t" \
        "mbarrier.try_wait.parity.acquire.cluster.shared::cta.b64 p, [%1], %2;\n\t" \
        "selp.b32 %0, 1, 0, p;\n\t" \
        "}" \
        : "=r"(_done) : "r"(_mbar), "r"(_parity) : "memory"); \
    if (!_done) { \
        asm volatile( \
            "{\n\t" \
            ".reg .pred P1;\n\t" \
            "WAIT_LOOP_%=:\n\t" \
            "mbarrier.try_wait.parity.acquire.cluster.shared::cta.b64 P1, [%0], %1, 0x989680;\n\t" \
            "@P1 bra.uni WAIT_DONE_%=;\n\t" \
            "bra.uni WAIT_LOOP_%=;\n\t" \
            "WAIT_DONE_%=:\n\t" \
            "}" \
            :: "r"(_mbar), "r"(_parity) : "memory"); \
    } \
} while (0)

#define MBARRIER_ARRIVE_CLUSTER(local_mbar_addr, target_rank) \
    asm volatile( \
        "{\n\t" \
        ".reg .b32 remAddr;\n\t" \
        "mapa.shared::cluster.u32 remAddr, %0, %1;\n\t" \
        "mbarrier.arrive.shared::cluster.b64 _, [remAddr];\n\t" \
        "}" \
        :: "r"((uint32_t)(local_mbar_addr)), "r"((uint32_t)(target_rank)) : "memory")

#define CLUSTER_SYNC() do { \
    asm volatile("barrier.cluster.arrive.aligned;" ::: "memory"); \
    asm volatile("barrier.cluster.wait.aligned;" ::: "memory"); \
} while (0)

#define TCGEN05_ALLOC_CG2(smem_result_addr, nCols) \
    asm volatile("tcgen05.alloc.cta_group::2.sync.aligned.shared::cta.b32 [%0], %1;" \
        :: "r"((uint32_t)(smem_result_addr)), "r"((uint32_t)(nCols)) : "memory")
#define TCGEN05_DEALLOC_CG2(tmem_addr, nCols) \
    asm volatile("tcgen05.dealloc.cta_group::2.sync.aligned.b32 %0, %1;" :: "r"(tmem_addr), "r"(nCols))
#define TCGEN05_RELINQUISH_CG2() \
    asm volatile("tcgen05.relinquish_alloc_permit.cta_group::2.sync.aligned;")
#define TCGEN05_COMMIT_MC_CG2(mbar_smem_addr, cta_mask) \
    asm volatile("tcgen05.commit.cta_group::2.mbarrier::arrive::one.shared::cluster.multicast::cluster.b64 [%0], %1;" \
        :: "r"((uint32_t)(mbar_smem_addr)), "h"((uint16_t)(cta_mask)) : "memory")
#define TCGEN05_WAIT_LD()  asm volatile("tcgen05.wait::ld.sync.aligned;" ::: "memory")
#define TCGEN05_FENCE_BEFORE() asm volatile("tcgen05.fence::before_thread_sync;" ::: "memory")
#define TCGEN05_FENCE_AFTER()  asm volatile("tcgen05.fence::after_thread_sync;" ::: "memory")
#define FENCE_PROXY_ASYNC_CTA() asm volatile("fence.proxy.async.shared::cta;" ::: "memory")

#define TCGEN05_LD_32X32B_X32(r, tmem_addr) \
    asm volatile( \
        "tcgen05.ld.sync.aligned.32x32b.x32.b32 " \
        "{%0, %1, %2, %3, %4, %5, %6, %7, " \
        " %8, %9, %10, %11, %12, %13, %14, %15, " \
        " %16, %17, %18, %19, %20, %21, %22, %23, " \
        " %24, %25, %26, %27, %28, %29, %30, %31}, [%32];" \
        : "=r"((r)[0]),  "=r"((r)[1]),  "=r"((r)[2]),  "=r"((r)[3]), \
          "=r"((r)[4]),  "=r"((r)[5]),  "=r"((r)[6]),  "=r"((r)[7]), \
          "=r"((r)[8]),  "=r"((r)[9]),  "=r"((r)[10]), "=r"((r)[11]), \
          "=r"((r)[12]), "=r"((r)[13]), "=r"((r)[14]), "=r"((r)[15]), \
          "=r"((r)[16]), "=r"((r)[17]), "=r"((r)[18]), "=r"((r)[19]), \
          "=r"((r)[20]), "=r"((r)[21]), "=r"((r)[22]), "=r"((r)[23]), \
          "=r"((r)[24]), "=r"((r)[25]), "=r"((r)[26]), "=r"((r)[27]), \
          "=r"((r)[28]), "=r"((r)[29]), "=r"((r)[30]), "=r"((r)[31]) \
        : "r"(tmem_addr))

// SW128 SMEM descriptor (K-major, version=1, SBO=64, LBO=1)
static constexpr uint64_t SMEM_DESC_BASE_SW128 =
    (uint64_t(2)  << 61) | (uint64_t(1) << 46) | (uint64_t(64) << 32) | (uint64_t(1) << 16);
#define MAKE_SMEM_DESC(base_addr) (SMEM_DESC_BASE_SW128 | ((uint64_t)((base_addr) >> 4) & 0x3FFF))

// cg2 bf16 SS MMA (fp32 accumulate), 8 disable-output-lane regs = 0
static __device__ __forceinline__ void mma_f16_ss_cg2(
    uint32_t d_tmem, uint64_t a_desc, uint64_t b_desc, uint32_t idesc, bool acc)
{
    uint32_t en = acc ? 1u : 0u;
    asm volatile(
        "{\n\t"
        ".reg .pred p;\n\t"
        "setp.ne.u32 p, %4, 0;\n\t"
        "tcgen05.mma.cta_group::2.kind::f16 [%0], %1, %2, %3, "
        "{%5, %5, %5, %5, %5, %5, %5, %5}, p;\n\t"
        "}"
        :: "r"(d_tmem), "l"(a_desc), "l"(b_desc), "r"(idesc), "r"(en), "r"(0u)
        : "memory");
}
#endif // USE_TCGEN05

// idesc: dtype=F32(1<<4), atype=BF16(1<<7), btype=BF16(1<<10), N/8<<17, M/16<<24 (M=256)
static constexpr uint32_t MMA_IDESC2 =
    0x490u | ((TN / 8) << 17) | ((TMP / 16) << 24);

// ---------------- kernel 0: zero the output (split-K accumulates) -----------
__global__ void __launch_bounds__(256) zero_out_kernel(float* __restrict__ out)
{
    size_t i = (size_t)blockIdx.x * blockDim.x + threadIdx.x;
    reinterpret_cast<float4*>(out)[i] = make_float4(0.f, 0.f, 0.f, 0.f);
}

// ---------------- kernel 1: A = w*inci + b  ->  bf16 hi/lo split -------------
__global__ void __launch_bounds__(256) split_A_kernel(
    const float* __restrict__ w, const float* __restrict__ inci, const float* __restrict__ b)
{
    size_t i = (size_t)blockIdx.x * blockDim.x + threadIdx.x;   // float4 index
    float4 wv = reinterpret_cast<const float4*>(w)[i];
    float4 iv = reinterpret_cast<const float4*>(inci)[i];
    float4 bv = reinterpret_cast<const float4*>(b)[i];
    float a0 = fmaf(wv.x, iv.x, bv.x);
    float a1 = fmaf(wv.y, iv.y, bv.y);
    float a2 = fmaf(wv.z, iv.z, bv.z);
    float a3 = fmaf(wv.w, iv.w, bv.w);

    __nv_bfloat16 h0 = __float2bfloat16(a0), h1 = __float2bfloat16(a1);
    __nv_bfloat16 h2 = __float2bfloat16(a2), h3 = __float2bfloat16(a3);
    __nv_bfloat16 l0 = __float2bfloat16(a0 - __bfloat162float(h0));
    __nv_bfloat16 l1 = __float2bfloat16(a1 - __bfloat162float(h1));
    __nv_bfloat16 l2 = __float2bfloat16(a2 - __bfloat162float(h2));
    __nv_bfloat16 l3 = __float2bfloat16(a3 - __bfloat162float(h3));

    ushort4 hv = make_ushort4(__bfloat16_as_ushort(h0), __bfloat16_as_ushort(h1),
                              __bfloat16_as_ushort(h2), __bfloat16_as_ushort(h3));
    ushort4 lv = make_ushort4(__bfloat16_as_ushort(l0), __bfloat16_as_ushort(l1),
                              __bfloat16_as_ushort(l2), __bfloat16_as_ushort(l3));
    reinterpret_cast<ushort4*>(g_Ahi)[i] = hv;
    reinterpret_cast<ushort4*>(g_Alo)[i] = lv;
}

// ---------------- kernel 2: xe = relu(in @ W + bias), transposed + split -----
__global__ void __launch_bounds__(1024) xe_kernel(
    const float* __restrict__ in, const float* __restrict__ W, const float* __restrict__ bx)
{
    __shared__ float Ws[DIMIN][DH];        // [64][32]
    __shared__ float ins[32][DIMIN];       // [32][64]
    __shared__ uint32_t tr[32][33];        // [h][e_local], padded

    int tx = threadIdx.x, ty = threadIdx.y;
    int e0 = blockIdx.x * 32;
    int b  = blockIdx.y;
    int flat = ty * 32 + tx;

    reinterpret_cast<float*>(Ws)[flat]        = W[flat];
    reinterpret_cast<float*>(Ws)[flat + 1024] = W[flat + 1024];
    size_t row = ((size_t)b * EDIM + e0 + ty) * DIMIN;
    ins[ty][tx]      = in[row + tx];
    ins[ty][tx + 32] = in[row + tx + 32];
    __syncthreads();

    float acc = bx[tx];
#pragma unroll
    for (int d = 0; d < DIMIN; d++)
        acc = fmaf(ins[ty][d], Ws[d][tx], acc);
    acc = fmaxf(acc, 0.0f);

    __nv_bfloat16 h = __float2bfloat16(acc);
    __nv_bfloat16 l = __float2bfloat16(acc - __bfloat162float(h));
    tr[tx][ty] = (uint32_t)__bfloat16_as_ushort(h) | ((uint32_t)__bfloat16_as_ushort(l) << 16);
    __syncthreads();

    uint32_t v = tr[ty][tx];                // h = ty, e_local = tx
    size_t off = (size_t)(b * 32 + ty) * KDIM + e0 + tx;
    g_Xhi[off] = __ushort_as_bfloat16((unsigned short)(v & 0xffffu));
    g_Xlo[off] = __ushort_as_bfloat16((unsigned short)(v >> 16));
}

// ---------------- kernel 3: GEMM (cg2, split-K=2, atomicAdd epilogue) --------
#if USE_TCGEN05
// 128-row region (A hi or lo): 16KB = 1024 16B units
static __device__ __forceinline__ void load_regA(
    uint32_t sbase, const __nv_bfloat16* __restrict__ grow, int k0, int t)
{
#pragma unroll
    for (int j = 0; j < 8; j++) {
        int idx = j * 128 + t;
        int r = idx >> 3, g = idx & 7;
        const void* gp = grow + (size_t)r * KDIM + k0 + g * 8;
        uint32_t off = (uint32_t)(r * 128 + g * 16);
        uint32_t so  = sbase + (off ^ ((off >> 3) & 0x70));
        asm volatile("cp.async.cg.shared.global [%0], [%1], 16;" :: "r"(so), "l"(gp));
    }
}
// 64-row region (B hi or lo): 8KB = 512 16B units
static __device__ __forceinline__ void load_regB(
    uint32_t sbase, const __nv_bfloat16* __restrict__ grow, int k0, int t)
{
#pragma unroll
    for (int j = 0; j < 4; j++) {
        int idx = j * 128 + t;
        int r = idx >> 3, g = idx & 7;
        const void* gp = grow + (size_t)r * KDIM + k0 + g * 8;
        uint32_t off = (uint32_t)(r * 128 + g * 16);
        uint32_t so  = sbase + (off ^ ((off >> 3) & 0x70));
        asm volatile("cp.async.cg.shared.global [%0], [%1], 16;" :: "r"(so), "l"(gp));
    }
}
#endif

__global__ void __launch_bounds__(160, 1) __cluster_dims__(2, 1, 1)
gemm_kernel(float* __restrict__ out)
{
    extern __shared__ char smem[];
    const int tid = threadIdx.x;

#if USE_TCGEN05
    uint32_t rank;
    asm("mov.u32 %0, %%cluster_ctarank;" : "=r"(rank));
    const int pm = blockIdx.x >> 1;            // pair id: m0 = pm*256
    const int m0 = pm * TMP;
    const int c0 = blockIdx.y * TN;
    const int kbase = blockIdx.z * CHUNKS * BK;

    uint32_t sb = smem_u32(smem);
    // layout: tmemptr@0, full[s]@16+8s, empty[s]@48+8s, done@80
    if (tid == 0) {
#pragma unroll
        for (int s = 0; s < STAGES; s++) {
            MBARRIER_INIT(sb + 16 + 8 * s, (rank == 0) ? 129u : 128u);  // +1 relay on rank0
            MBARRIER_INIT(sb + 48 + 8 * s, 1);
        }
        MBARRIER_INIT(sb + 80, 1);
    }
    __syncthreads();
    CLUSTER_SYNC();                            // barriers visible cluster-wide

    if ((tid >> 5) == 0) TCGEN05_ALLOC_CG2(sb + 0, 128);
    __syncthreads();
    uint32_t tmem;
    asm volatile("ld.shared.b32 %0, [%1];" : "=r"(tmem) : "r"(sb + 0));

    if (tid < 128) {
        // ---- producers: this CTA's 128 A-rows and its 64-row B half ----
        const __nv_bfloat16* gA0 = g_Ahi + (size_t)(m0 + rank * 128) * KDIM;
        const __nv_bfloat16* gA1 = g_Alo + (size_t)(m0 + rank * 128) * KDIM;
        const __nv_bfloat16* gB0 = g_Xhi + (size_t)(c0 + rank * 64) * KDIM;
        const __nv_bfloat16* gB1 = g_Xlo + (size_t)(c0 + rank * 64) * KDIM;
        int s = 0, ph = 1;                     // first empty-wait passes immediately
        for (int ch = 0; ch < CHUNKS; ch++) {
            MBARRIER_WAIT_PARITY(sb + 48 + 8 * s, ph);
            uint32_t stb = sb + SMEM_STAGE0 + s * STAGE_BYTES;
            int k0 = kbase + ch * BK;
            load_regA(stb,             gA0, k0, tid);
            load_regA(stb + A_REG,     gA1, k0, tid);
            load_regB(stb + 2 * A_REG,         gB0, k0, tid);
            load_regB(stb + 2 * A_REG + B_REG, gB1, k0, tid);
            asm volatile("cp.async.mbarrier.arrive.noinc.shared::cta.b64 [%0];"
                         :: "r"(sb + 16 + 8 * s) : "memory");
            if (++s == STAGES) { s = 0; ph ^= 1; }
        }
    } else if (tid == 128) {
        if (rank == 0) {
            // ---- consumer: single-thread cg2 MMA issuer ----
            int s = 0, ph = 0;
            bool first = true;
            for (int ch = 0; ch < CHUNKS; ch++) {
                MBARRIER_WAIT_PARITY_CLU(sb + 16 + 8 * s, ph);  // 128 local + 1 relay
                FENCE_PROXY_ASYNC_CTA();
                uint32_t stb = sb + SMEM_STAGE0 + s * STAGE_BYTES;
                uint64_t dAh = MAKE_SMEM_DESC(stb);
                uint64_t dAl = MAKE_SMEM_DESC(stb + A_REG);
                uint64_t dBh = MAKE_SMEM_DESC(stb + 2 * A_REG);
                uint64_t dBl = MAKE_SMEM_DESC(stb + 2 * A_REG + B_REG);
#pragma unroll
                for (int k = 0; k < 4; k++) {   // 4 x K16 per 64-K chunk
                    mma_f16_ss_cg2(tmem, dAh + k * 2, dBh + k * 2, MMA_IDESC2, !first);
                    first = false;
                    mma_f16_ss_cg2(tmem, dAh + k * 2, dBl + k * 2, MMA_IDESC2, true);
                    mma_f16_ss_cg2(tmem, dAl + k * 2, dBh + k * 2, MMA_IDESC2, true);
                }
                TCGEN05_COMMIT_MC_CG2(sb + 48 + 8 * s, 0x3);   // free stage in BOTH CTAs
                if (++s == STAGES) { s = 0; ph ^= 1; }
            }
            TCGEN05_COMMIT_MC_CG2(sb + 80, 0x3);               // done, both CTAs
        } else {
            // ---- relay (rank 1): local full -> arrive on rank0's full ----
            int s = 0, ph = 0;
            for (int ch = 0; ch < CHUNKS; ch++) {
                MBARRIER_WAIT_PARITY(sb + 16 + 8 * s, ph);
                FENCE_PROXY_ASYNC_CTA();       // order this CTA's smem for async-proxy reads
                MBARRIER_ARRIVE_CLUSTER(sb + 16 + 8 * s, 0);
                if (++s == STAGES) { s = 0; ph ^= 1; }
            }
        }
    }

    __syncthreads();
    MBARRIER_WAIT_PARITY(sb + 80, 0);
    TCGEN05_FENCE_AFTER();

    if (tid < 128) {
        // each CTA reads its own 128x128 D from TMEM; atomicAdd (split-K partial)
        int n = m0 + (int)rank * 128 + tid;
#pragma unroll
        for (int p = 0; p < 4; p++) {
            uint32_t r[32];
            TCGEN05_LD_32X32B_X32(r, tmem + p * 32);
            TCGEN05_WAIT_LD();
            int bb = (c0 >> 5) + p;            // batch for this 32-col group
            float* o = out + (((size_t)bb * NNODE + n) << 5);
#pragma unroll
            for (int q = 0; q < 32; q++)
                atomicAdd(o + q, __uint_as_float(r[q]));
        }
        TCGEN05_FENCE_BEFORE();
    }
    __syncthreads();
    if ((tid >> 5) == 0) {
        TCGEN05_RELINQUISH_CG2();
        TCGEN05_DEALLOC_CG2(tmem, 128);
    }
    CLUSTER_SYNC();                            // no CTA exits with peer ops in flight
#else
    // ---------------- SIMT fp32 fallback (non-'a' compilation pass) ----------
    const int m0f = blockIdx.x * 128;
    const int c0f = blockIdx.y * TN;
    const int kbasef = blockIdx.z * CHUNKS * BK;
    if (tid >= 128) return;
    float* As = reinterpret_cast<float*>(smem);            // [128][65]
    float* Bs = As + 128 * 65;                             // [64][128]

    const int tx = tid & 7;        // n-group: 16 cols
    const int ty = tid >> 3;       // m-group: 8 rows
    float acc[8][16];
#pragma unroll
    for (int i = 0; i < 8; i++)
#pragma unroll
        for (int j = 0; j < 16; j++) acc[i][j] = 0.0f;

    for (int ch = 0; ch < CHUNKS; ch++) {
        int k0 = kbasef + ch * BK;
        {
            const uint4* ph4 = reinterpret_cast<const uint4*>(g_Ahi + (size_t)(m0f + tid) * KDIM + k0);
            const uint4* pl4 = reinterpret_cast<const uint4*>(g_Alo + (size_t)(m0f + tid) * KDIM + k0);
#pragma unroll
            for (int v = 0; v < 8; v++) {
                uint4 hv = ph4[v], lv = pl4[v];
                const unsigned short* hs = reinterpret_cast<const unsigned short*>(&hv);
                const unsigned short* ls = reinterpret_cast<const unsigned short*>(&lv);
#pragma unroll
                for (int e = 0; e < 8; e++)
                    As[tid * 65 + v * 8 + e] =
                        __bfloat162float(__ushort_as_bfloat16(hs[e])) +
                        __bfloat162float(__ushort_as_bfloat16(ls[e]));
            }
        }
        {
            const uint4* ph4 = reinterpret_cast<const uint4*>(g_Xhi + (size_t)(c0f + tid) * KDIM + k0);
            const uint4* pl4 = reinterpret_cast<const uint4*>(g_Xlo + (size_t)(c0f + tid) * KDIM + k0);
#pragma unroll
            for (int v = 0; v < 8; v++) {
                uint4 hv = ph4[v], lv = pl4[v];
                const unsigned short* hs = reinterpret_cast<const unsigned short*>(&hv);
                const unsigned short* ls = reinterpret_cast<const unsigned short*>(&lv);
#pragma unroll
                for (int e = 0; e < 8; e++)
                    Bs[(v * 8 + e) * 128 + tid] =
                        __bfloat162float(__ushort_as_bfloat16(hs[e])) +
                        __bfloat162float(__ushort_as_bfloat16(ls[e]));
            }
        }
        asm volatile("bar.sync 1, 128;" ::: "memory");
#pragma unroll 4
        for (int k = 0; k < BK; k++) {
            float a[8], bvx[16];
#pragma unroll
            for (int i = 0; i < 8; i++) a[i] = As[(ty * 8 + i) * 65 + k];
#pragma unroll
            for (int j = 0; j < 16; j++) bvx[j] = Bs[k * 128 + tx * 16 + j];
#pragma unroll
            for (int i = 0; i < 8; i++)
#pragma unroll
                for (int j = 0; j < 16; j++)
                    acc[i][j] = fmaf(a[i], bvx[j], acc[i][j]);
        }
        asm volatile("bar.sync 1, 128;" ::: "memory");
    }
#pragma unroll
    for (int i = 0; i < 8; i++) {
        int n = m0f + ty * 8 + i;
#pragma unroll
        for (int j = 0; j < 16; j++) {
            int c = c0f + tx * 16 + j;
            atomicAdd(&out[(((size_t)(c >> 5) * NNODE + n) << 5) + (c & 31)], acc[i][j]);
        }
    }
#endif
}

// ---------------- launch ----------------------------------------------------
extern "C" void kernel_launch(void* const* d_in, const int* in_sizes, int n_in,
                              void* d_out, int out_size)
{
    const float* inputs = (const float*)d_in[0];   // [16, 8192, 64]
    const float* W_xes  = (const float*)d_in[1];   // [64, 32]
    const float* b_xes  = (const float*)d_in[2];   // [32]
    const float* inci   = (const float*)d_in[3];   // [2048, 8192]
    const float* w      = (const float*)d_in[4];   // [2048, 8192]
    const float* b      = (const float*)d_in[5];   // [2048, 8192]
    float* out = (float*)d_out;                    // [16, 2048, 32]

    // 0) zero output (split-K accumulates with atomicAdd)
    zero_out_kernel<<<(NNODE * NDIM / 4) / 256, 256>>>(out);
    // 1) A = w*inci + b -> bf16 hi/lo
    {
        size_t n4 = (size_t)MDIM * KDIM / 4;
        split_A_kernel<<<(unsigned)(n4 / 256), 256>>>(w, inci, b);
    }
    // 2) xe = relu(inputs @ W + bias), transposed to [c][e], bf16 hi/lo
    {
        dim3 grid(EDIM / 32, BQ), blk(32, 32);
        xe_kernel<<<grid, blk>>>(inputs, W_xes, b_xes);
    }
    // 3) cg2 GEMM, split-K=2: grid (16 CTAs = 8 pairs, 4 cols, 2 k-halves)
    {
        cudaFuncSetAttribute(gemm_kernel, cudaFuncAttributeMaxDynamicSharedMemorySize, SMEM_DYN);
        dim3 grid(MDIM / TMP * 2, NDIM / TN, KSPLIT);   // (16, 4, 2)
        gemm_kernel<<<grid, 160, SMEM_DYN>>>(out);
    }
}